// round 17
// baseline (speedup 1.0000x reference)
#include <cuda_runtime.h>
#include <cuda_fp16.h>
#include <math.h>
#include <stdint.h>

// ---------------- problem constants ----------------
#define BSZ   4
#define TN    512
#define BT    2048
#define EMB   256
#define NH    8
#define HD    32
#define HID   1024
#define VOC   50257
#define VOCP  50432

#define LOSS_OFF ((size_t)BT * VOC)
#define PROB_OFF (LOSS_OFF + 1)

// ---------------- device scratch ----------------
__device__ float g_q [NH * BT * HD];
__device__ float g_k [NH * BT * HD];
__device__ float g_v [NH * BT * HD];
__device__ float g_sT[NH * BSZ * TN * TN];   // [n][b][s][t]
__device__ float g_zs[NH * BSZ * TN];        // per-(n,b,s) sum of exp over t
__device__ float g_ao[BT * EMB];
__device__ __half g_w1t[(size_t)HID * EMB];  // W1^T fp16 [n][k]
__device__ __half g_h  [BT * HID];
__device__ __half g_w2t[(size_t)VOCP * HID];
__device__ float g_z [BT];

// fast exp for |x| small; guarded exact fallback
__device__ __forceinline__ float fexp(float x) {
    if (fabsf(x) > 0.25f) return __expf(x);
    float p = fmaf(x, 0.041666667f, 0.16666667f);
    p = fmaf(x, p, 0.5f);
    p = fmaf(x, p, 1.0f);
    p = fmaf(x, p, 1.0f);
    return p;
}

__device__ __forceinline__ uint32_t s2u(const void* p) {
    uint32_t a;
    asm("{ .reg .u64 t; cvta.to.shared.u64 t, %1; cvt.u32.u64 %0, t; }" : "=r"(a) : "l"(p));
    return a;
}
__device__ __forceinline__ void ldgsts16(uint32_t s, const void* g) {
    asm volatile("cp.async.cg.shared.global [%0], [%1], 16;" :: "r"(s), "l"(g));
}
#define CP_COMMIT() asm volatile("cp.async.commit_group;" ::: "memory")
#define CP_WAIT(n)  asm volatile("cp.async.wait_group %0;" :: "n"(n) : "memory")

#define LDSM4(r0, r1, r2, r3, addr) \
    asm volatile("ldmatrix.sync.aligned.m8n8.x4.shared.b16 {%0,%1,%2,%3}, [%4];" \
                 : "=r"(r0), "=r"(r1), "=r"(r2), "=r"(r3) : "r"(addr))

__device__ __forceinline__ void mma_fp16(float* d, const uint32_t* a, const uint32_t* b) {
    asm volatile(
        "mma.sync.aligned.m16n8k16.row.col.f32.f16.f16.f32 "
        "{%0,%1,%2,%3}, {%4,%5,%6,%7}, {%8,%9}, {%0,%1,%2,%3};"
        : "+f"(d[0]), "+f"(d[1]), "+f"(d[2]), "+f"(d[3])
        : "r"(a[0]), "r"(a[1]), "r"(a[2]), "r"(a[3]), "r"(b[0]), "r"(b[1]));
}

__device__ __forceinline__ void stcs(float* p, float v) {
    asm volatile("st.global.cs.f32 [%0], %1;" :: "l"(p), "f"(v));
}
__device__ __forceinline__ float ldcs(const float* p) {
    float v;
    asm volatile("ld.global.cs.f32 %0, [%1];" : "=f"(v) : "l"(p));
    return v;
}

// ---------------- 64x64 transpose tiles (run inside attention kernels) -----
#define W2T_NB 788                      // VOCP/64
#define W2T_TILES (W2T_NB * 16)         // 12608
#define W2T_HALF 6304
#define W1T_TILES 64                    // (HID/64)*(EMB/64)

__device__ __forceinline__ void w2_tile(int tt, const float* __restrict__ W2,
                                        float (*tb)[65]) {
    int tid = threadIdx.x;
    int nb = (tt % W2T_NB) * 64, kb = (tt / W2T_NB) * 64;
    int r = tid >> 2, c0 = (tid & 3) * 16;
    #pragma unroll
    for (int i = 0; i < 16; i++) {
        int n = nb + c0 + i;
        tb[r][c0 + i] = (n < VOC) ? W2[(size_t)(kb + r) * VOC + n] : 0.f;
    }
    __syncthreads();
    __half hv[16];
    #pragma unroll
    for (int i = 0; i < 16; i++)
        hv[i] = __float2half_rn(tb[c0 + i][r]);
    *(uint4*)&g_w2t[(size_t)(nb + r) * HID + kb + c0]     = *(uint4*)&hv[0];
    *(uint4*)&g_w2t[(size_t)(nb + r) * HID + kb + c0 + 8] = *(uint4*)&hv[8];
}

__device__ __forceinline__ void w1_tile(int tt, const float* __restrict__ W1,
                                        float (*tb)[65]) {
    int tid = threadIdx.x;
    int nb = (tt & 15) * 64, kb = (tt >> 4) * 64;
    int r = tid >> 2, c0 = (tid & 3) * 16;
    #pragma unroll
    for (int i = 0; i < 4; i++) {
        float4 v = *(const float4*)&W1[(size_t)(kb + r) * HID + nb + c0 + i * 4];
        tb[r][c0 + i * 4 + 0] = v.x; tb[r][c0 + i * 4 + 1] = v.y;
        tb[r][c0 + i * 4 + 2] = v.z; tb[r][c0 + i * 4 + 3] = v.w;
    }
    __syncthreads();
    __half hv[16];
    #pragma unroll
    for (int i = 0; i < 16; i++)
        hv[i] = __float2half_rn(tb[c0 + i][r]);
    *(uint4*)&g_w1t[(size_t)(nb + r) * EMB + kb + c0]     = *(uint4*)&hv[0];
    *(uint4*)&g_w1t[(size_t)(nb + r) * EMB + kb + c0 + 8] = *(uint4*)&hv[8];
}

// ================= launch 1: qkv (fused embed) + zeroing =================
#define QKV_BLOCKS 768
#define ZERO_BLOCKS 2048

__global__ void __launch_bounds__(256)
k_fused1(const int* __restrict__ idx,
         const float* __restrict__ tok,
         const float* __restrict__ pos,
         const float* __restrict__ Wq,
         const float* __restrict__ Wk,
         const float* __restrict__ Wv,
         float* __restrict__ out) {
    int tid = threadIdx.x;
    int bid = blockIdx.x;

    if (bid >= QKV_BLOCKS) {
        int zb = bid - QKV_BLOCKS;
        g_ao[zb * 256 + tid] = 0.f;
        if (zb < 64) g_zs[zb * 256 + tid] = 0.f;
        if (zb < 8)  g_z [zb * 256 + tid] = 0.f;
        if (zb == 0 && tid == 0) out[LOSS_OFF] = 0.f;
        return;
    }

    __shared__ float As[64][65];
    __shared__ float Ws[64][33];
    int t0 = (bid & 31) * 64;
    int n = (bid >> 5) & 7;
    int w = bid >> 8;
    const float* W = (w == 0) ? Wq : (w == 1) ? Wk : Wv;
    const float* Wn = W + (size_t)n * EMB * HD;
    float* dst = (w == 0) ? g_q : (w == 1) ? g_k : g_v;

    int tx = tid & 15, ty = tid >> 4;
    float acc[4][2];
    #pragma unroll
    for (int i = 0; i < 4; i++) { acc[i][0] = 0.f; acc[i][1] = 0.f; }

    for (int kc = 0; kc < EMB; kc += 64) {
        {
            int r = tid >> 2, c0 = (tid & 3) * 16;
            int ti = t0 + r;
            int id = idx[ti];
            const float* te = &tok[(size_t)id * EMB + kc + c0];
            const float* pe = &pos[(size_t)(ti & (TN - 1)) * EMB + kc + c0];
            #pragma unroll
            for (int i = 0; i < 4; i++) {
                float4 a = *(const float4*)(te + i * 4);
                float4 p = *(const float4*)(pe + i * 4);
                As[r][c0 + i * 4 + 0] = a.x + p.x;
                As[r][c0 + i * 4 + 1] = a.y + p.y;
                As[r][c0 + i * 4 + 2] = a.z + p.z;
                As[r][c0 + i * 4 + 3] = a.w + p.w;
            }
        }
        {
            int r = tid >> 2, c0 = (tid & 3) * 8;
            const float* src = &Wn[(size_t)(kc + r) * HD + c0];
            #pragma unroll
            for (int i = 0; i < 2; i++) {
                float4 v = *(const float4*)(src + i * 4);
                Ws[r][c0 + i * 4 + 0] = v.x; Ws[r][c0 + i * 4 + 1] = v.y;
                Ws[r][c0 + i * 4 + 2] = v.z; Ws[r][c0 + i * 4 + 3] = v.w;
            }
        }
        __syncthreads();
        #pragma unroll 8
        for (int k = 0; k < 64; k++) {
            float a0 = As[ty * 4 + 0][k];
            float a1 = As[ty * 4 + 1][k];
            float a2 = As[ty * 4 + 2][k];
            float a3 = As[ty * 4 + 3][k];
            float b0 = Ws[k][tx * 2 + 0];
            float b1 = Ws[k][tx * 2 + 1];
            acc[0][0] += a0 * b0; acc[0][1] += a0 * b1;
            acc[1][0] += a1 * b0; acc[1][1] += a1 * b1;
            acc[2][0] += a2 * b0; acc[2][1] += a2 * b1;
            acc[3][0] += a3 * b0; acc[3][1] += a3 * b1;
        }
        __syncthreads();
    }
    #pragma unroll
    for (int i = 0; i < 4; i++) {
        size_t row = (size_t)n * BT + t0 + ty * 4 + i;
        dst[row * HD + tx * 2 + 0] = acc[i][0];
        dst[row * HD + tx * 2 + 1] = acc[i][1];
    }
}

// ================= scores + z-sums, plus W1T + first half of W2T ==========
#define NSCORE 2048

__global__ void __launch_bounds__(256)
k_score2x(const float* __restrict__ W1, const float* __restrict__ W2) {
    __shared__ float sb[64 * 66 + 64 * 65];   // Qs,Ks | Os ; alias for transpose
    int tid = threadIdx.x;
    int bid = blockIdx.x;

    if (bid >= NSCORE) {
        int tt = bid - NSCORE;
        float (*Tb)[65] = (float(*)[65])sb;
        if (tt < W1T_TILES) w1_tile(tt, W1, Tb);
        else                w2_tile(tt - W1T_TILES, W2, Tb);
        return;
    }

    float (*Qs)[33] = (float(*)[33])sb;
    float (*Ks)[33] = (float(*)[33])(sb + 64 * 33);
    float (*Os)[65] = (float(*)[65])(sb + 64 * 66);

    int bi = bid & 7;
    int bj = (bid >> 3) & 7;
    int b = (bid >> 6) & 3, n = (bid >> 8) & 7;
    int t0 = bi * 64, s0 = bj * 64;
    size_t nb_off = ((size_t)(n * BSZ + b)) * TN;
    float* dst = &g_sT[(nb_off + s0) * TN + t0];

    if (t0 + 63 < s0) {
        #pragma unroll
        for (int r = 0; r < 16; r++) {
            int idx = tid + r * 256;
            dst[(size_t)(idx >> 6) * TN + (idx & 63)] = -1e30f;
        }
        return;
    }

    int base = n * BT + b * TN;
    {
        int r = tid >> 2;
        int c = (tid & 3) * 8;
        const float* qp = &g_q[((size_t)(base + t0 + r)) * HD + c];
        const float* kp = &g_k[((size_t)(base + s0 + r)) * HD + c];
        float4 v0 = *(const float4*)qp, v1 = *(const float4*)(qp + 4);
        Qs[r][c + 0] = v0.x; Qs[r][c + 1] = v0.y; Qs[r][c + 2] = v0.z; Qs[r][c + 3] = v0.w;
        Qs[r][c + 4] = v1.x; Qs[r][c + 5] = v1.y; Qs[r][c + 6] = v1.z; Qs[r][c + 7] = v1.w;
        v0 = *(const float4*)kp; v1 = *(const float4*)(kp + 4);
        Ks[r][c + 0] = v0.x; Ks[r][c + 1] = v0.y; Ks[r][c + 2] = v0.z; Ks[r][c + 3] = v0.w;
        Ks[r][c + 4] = v1.x; Ks[r][c + 5] = v1.y; Ks[r][c + 6] = v1.z; Ks[r][c + 7] = v1.w;
    }
    __syncthreads();

    int tx = tid & 15, ty = tid >> 4;
    float acc[4][4];
    #pragma unroll
    for (int i = 0; i < 4; i++)
        #pragma unroll
        for (int j = 0; j < 4; j++) acc[i][j] = 0.f;

    #pragma unroll
    for (int h = 0; h < HD; h++) {
        float a[4], c[4];
        #pragma unroll
        for (int i = 0; i < 4; i++) a[i] = Qs[ty * 4 + i][h];
        #pragma unroll
        for (int j = 0; j < 4; j++) c[j] = Ks[tx * 4 + j][h];
        #pragma unroll
        for (int i = 0; i < 4; i++)
            #pragma unroll
            for (int j = 0; j < 4; j++) acc[i][j] += a[i] * c[j];
    }

    #pragma unroll
    for (int i = 0; i < 4; i++)
        #pragma unroll
        for (int j = 0; j < 4; j++) {
            int tt = ty * 4 + i, ss = tx * 4 + j;
            Os[ss][tt] = (t0 + tt >= s0 + ss) ? acc[i][j] * 0.0625f : -1e30f;
        }
    __syncthreads();

    {
        int ss = tid & 63, qq = tid >> 6;
        float part = 0.f;
        #pragma unroll
        for (int tt = qq * 16; tt < qq * 16 + 16; tt++) part += __expf(Os[ss][tt]);
        Qs[ss][qq] = part;
    }
    #pragma unroll
    for (int r = 0; r < 16; r++) {
        int idx = tid + r * 256;
        int ss = idx >> 6, tt = idx & 63;
        dst[(size_t)ss * TN + tt] = Os[ss][tt];
    }
    __syncthreads();
    if (tid < 64) {
        float zsum = Qs[tid][0] + Qs[tid][1] + Qs[tid][2] + Qs[tid][3];
        atomicAdd(&g_zs[nb_off + s0 + tid], zsum);
    }
}

// ================= attention out + second half of W2T =====================
#define NATT 1024

__global__ void __launch_bounds__(256)
k_attnout3x(const float* __restrict__ W2) {
    __shared__ float sb[64 * 65 + 64 * 33 + 64];
    int tid = threadIdx.x;
    int bid = blockIdx.x;

    if (bid >= NATT) {
        float (*Tb)[65] = (float(*)[65])sb;
        w2_tile(bid - NATT + W2T_HALF, W2, Tb);
        return;
    }

    float (*Ws)[65] = (float(*)[65])sb;
    float (*Vs)[33] = (float(*)[33])(sb + 64 * 65);
    float* zr = sb + 64 * 65 + 64 * 33;

    int bt = bid & 7;
    int q = (bid >> 3) & 3;
    if (q > bt) return;
    int z = bid >> 5;
    int b = z & 3, n = z >> 2;
    int t0 = bt * 64;
    size_t nb = (size_t)n * BSZ + b;
    const float* sT = &g_sT[nb * TN * TN];
    const float* v  = &g_v[((size_t)n * BT + b * TN) * HD];

    int tx = tid & 15, ty = tid >> 4;
    float acc[4][2];
    #pragma unroll
    for (int i = 0; i < 4; i++) { acc[i][0] = 0.f; acc[i][1] = 0.f; }

    for (int sb2 = q; sb2 <= bt; sb2 += 4) {
        int s0 = sb2 * 64;
        if (tid < 64)
            zr[tid] = 1.0f / g_zs[nb * TN + s0 + tid];
        __syncthreads();
        #pragma unroll
        for (int r = 0; r < 16; r++) {
            int idx = tid + r * 256;
            int ss = idx >> 6, tt = idx & 63;
            float sv = sT[(size_t)(s0 + ss) * TN + t0 + tt];
            Ws[ss][tt] = __expf(sv) * zr[ss];
        }
        {
            int r = tid >> 2;
            int c = (tid & 3) * 8;
            const float* vp = &v[(size_t)(s0 + r) * HD + c];
            float4 v0 = *(const float4*)vp, v1 = *(const float4*)(vp + 4);
            Vs[r][c + 0] = v0.x; Vs[r][c + 1] = v0.y; Vs[r][c + 2] = v0.z; Vs[r][c + 3] = v0.w;
            Vs[r][c + 4] = v1.x; Vs[r][c + 5] = v1.y; Vs[r][c + 6] = v1.z; Vs[r][c + 7] = v1.w;
        }
        __syncthreads();
        #pragma unroll 8
        for (int ss = 0; ss < 64; ss++) {
            float w0 = Ws[ss][ty * 4 + 0];
            float w1 = Ws[ss][ty * 4 + 1];
            float w2 = Ws[ss][ty * 4 + 2];
            float w3 = Ws[ss][ty * 4 + 3];
            float va = Vs[ss][tx * 2 + 0];
            float vb = Vs[ss][tx * 2 + 1];
            acc[0][0] += w0 * va; acc[0][1] += w0 * vb;
            acc[1][0] += w1 * va; acc[1][1] += w1 * vb;
            acc[2][0] += w2 * va; acc[2][1] += w2 * vb;
            acc[3][0] += w3 * va; acc[3][1] += w3 * vb;
        }
        __syncthreads();
    }

    #pragma unroll
    for (int i = 0; i < 4; i++) {
        int t = t0 + ty * 4 + i;
        int h = tx * 2;
        float* op = &g_ao[((size_t)(b * TN + t)) * EMB + n * HD + h];
        atomicAdd(op + 0, acc[i][0]);
        atomicAdd(op + 1, acc[i][1]);
    }
}

// ================= FF1 via fp16 tensor cores (32-row tiles) ===============
#define FF_SA 264                       // halves per row (256 + 8 pad)
#define FF_A_H (32 * FF_SA)             // 8448 halves
#define FF_B_H (64 * FF_SA)             // 16896 halves
#define FF_SMEM ((FF_A_H + FF_B_H) * 2) // 50688 bytes

__global__ void __launch_bounds__(256)
k_ff1d(const float* __restrict__ b1) {
    extern __shared__ __half ff_smem_buf[];
    uint32_t smb = s2u(ff_smem_buf);
    int tid = threadIdx.x;
    int wid = tid >> 5, lane = tid & 31;
    int wm = wid & 1, wn = wid >> 1;      // 2 x 4 warps: m 2x16, n 4x16
    int lq = lane >> 2, lr = lane & 3;
    int t0 = blockIdx.x * 32;
    int n0 = blockIdx.y * 64;

    // stage B FIRST (async): 64 rows x 256 halves
    {
        uint32_t bbase = smb + FF_A_H * 2u;
        #pragma unroll
        for (int i = 0; i < 8; i++) {
            int j = tid + i * 256;
            int row = j >> 5, ch = j & 31;
            ldgsts16(bbase + (uint32_t)(row * FF_SA + ch * 8) * 2u,
                     &g_w1t[(size_t)(n0 + row) * EMB + ch * 8]);
        }
        CP_COMMIT();
    }
    // stage A (overlaps): 32 rows x 256 fp32 -> fp16
    {
        int r = tid >> 3, c0 = (tid & 7) * 32;
        const float4* src = (const float4*)&g_ao[(size_t)(t0 + r) * EMB + c0];
        __half2* adst = (__half2*)(ff_smem_buf + r * FF_SA + c0);
        #pragma unroll
        for (int i = 0; i < 8; i++) {
            float4 v = src[i];
            adst[i * 2 + 0] = __floats2half2_rn(v.x, v.y);
            adst[i * 2 + 1] = __floats2half2_rn(v.z, v.w);
        }
    }
    CP_WAIT(0);
    __syncthreads();

    uint32_t lrow = (lane & 7) + ((lane >> 3) & 1) * 8;
    uint32_t lkh  = (lane >> 4) * 8;
    uint32_t aaddr = smb + ((wm * 16 + lrow) * FF_SA + lkh) * 2u;
    uint32_t baddr = smb + FF_A_H * 2u + ((wn * 16 + lrow) * FF_SA + lkh) * 2u;

    float acc[2][4];
    #pragma unroll
    for (int j = 0; j < 2; j++)
        #pragma unroll
        for (int q2 = 0; q2 < 4; q2++) acc[j][q2] = 0.f;

    #pragma unroll
    for (int k0 = 0; k0 < EMB; k0 += 16) {
        uint32_t a[4], b[2][2];
        LDSM4(a[0], a[1], a[2], a[3], aaddr + (uint32_t)k0 * 2u);
        LDSM4(b[0][0], b[1][0], b[0][1], b[1][1], baddr + (uint32_t)k0 * 2u);
        #pragma unroll
        for (int nt = 0; nt < 2; nt++)
            mma_fp16(acc[nt], a, b[nt]);
    }

    // epilogue: bias + relu + fp16
    int m0 = t0 + wm * 16 + lq;
    #pragma unroll
    for (int nt = 0; nt < 2; nt++) {
        int n = n0 + wn * 16 + nt * 8 + lr * 2;
        float bb0 = b1[n], bb1 = b1[n + 1];
        __half2 h0 = __floats2half2_rn(fmaxf(acc[nt][0] + bb0, 0.f),
                                       fmaxf(acc[nt][1] + bb1, 0.f));
        __half2 h1 = __floats2half2_rn(fmaxf(acc[nt][2] + bb0, 0.f),
                                       fmaxf(acc[nt][3] + bb1, 0.f));
        *(__half2*)&g_h[(size_t)m0 * HID + n] = h0;
        *(__half2*)&g_h[(size_t)(m0 + 8) * HID + n] = h1;
    }
}

// ================= fp16 m16n8k16 LM-head GEMM (ldmatrix, 3-stage) =======
#define MT    128
#define NTL   128
#define KCH   64
#define SAH   72
#define STAGE_H (MT * SAH)
#define STAGE_B2 (STAGE_H * 2)
#define GSMEM (6 * STAGE_B2)

__global__ void __launch_bounds__(256, 2)
k_gemm_tc(const float* __restrict__ b2, float* __restrict__ out) {
    extern __shared__ __half smh[];
    uint32_t smb = s2u(smh);
    int tid = threadIdx.x;
    int wid = tid >> 5, lane = tid & 31;
    int wm = wid & 3, wn = wid >> 2;
    int lq = lane >> 2, lr = lane & 3;
    int bm = blockIdx.x * MT;
    int bn = blockIdx.y * NTL;

    const __half* Ag = &g_h  [(size_t)bm * HID];
    const __half* Bg = &g_w2t[(size_t)bn * HID];

    uint32_t lrow = (lane & 7) + ((lane >> 3) & 1) * 8;
    uint32_t lkh  = (lane >> 4) * 8;

    float acc[2][8][4];
    #pragma unroll
    for (int i = 0; i < 2; i++)
        #pragma unroll
        for (int j = 0; j < 8; j++)
            #pragma unroll
            for (int q = 0; q < 4; q++) acc[i][j][q] = 0.f;

    auto load_chunk = [&](int st, int c) {
        uint32_t abase = smb + (uint32_t)st * 2u * STAGE_B2;
        uint32_t bbase = abase + STAGE_B2;
        #pragma unroll
        for (int i = 0; i < 4; i++) {
            int j = tid + i * 256;
            int row = j >> 3, f8 = j & 7;
            uint32_t so = (uint32_t)(row * SAH + f8 * 8) * 2u;
            size_t go = (size_t)row * HID + c * KCH + f8 * 8;
            ldgsts16(abase + so, Ag + go);
            ldgsts16(bbase + so, Bg + go);
        }
        CP_COMMIT();
    };

    load_chunk(0, 0);
    load_chunk(1, 1);

    const int NCH = HID / KCH;
    for (int c = 0; c < NCH; c++) {
        int st = c % 3;
        if (c + 1 < NCH) { CP_WAIT(1); } else { CP_WAIT(0); }
        __syncthreads();
        if (c + 2 < NCH) load_chunk((c + 2) % 3, c + 2);

        uint32_t sbase = smb + (uint32_t)st * 2u * STAGE_B2;
        uint32_t aaddr = sbase + ((wm * 32 + lrow) * SAH + lkh) * 2u;
        uint32_t baddr = sbase + STAGE_B2 + ((wn * 64 + lrow) * SAH + lkh) * 2u;

        #pragma unroll
        for (int k0 = 0; k0 < KCH; k0 += 16) {
            uint32_t a[2][4], b[8][2];
            #pragma unroll
            for (int mt = 0; mt < 2; mt++)
                LDSM4(a[mt][0], a[mt][1], a[mt][2], a[mt][3],
                      aaddr + (uint32_t)(mt * 16 * SAH + k0) * 2u);
            #pragma unroll
            for (int j = 0; j < 4; j++)
                LDSM4(b[2 * j][0], b[2 * j + 1][0], b[2 * j][1], b[2 * j + 1][1],
                      baddr + (uint32_t)(j * 16 * SAH + k0) * 2u);
            #pragma unroll
            for (int mt = 0; mt < 2; mt++)
                #pragma unroll
                for (int nt = 0; nt < 8; nt++)
                    mma_fp16(acc[mt][nt], a[mt], b[nt]);
        }
    }

    // epilogue: evict-first logit stores, poly-exp z accumulation
    float zp[4] = {0.f, 0.f, 0.f, 0.f};
    #pragma unroll
    for (int mt = 0; mt < 2; mt++) {
        int m0 = bm + wm * 32 + mt * 16 + lq;
        #pragma unroll
        for (int nt = 0; nt < 8; nt++) {
            int n = bn + wn * 64 + nt * 8 + lr * 2;
            if (n >= VOC) continue;
            float bb0 = b2[n];
            size_t o0 = (size_t)m0 * VOC + n;
            size_t o1 = (size_t)(m0 + 8) * VOC + n;
            float v00 = acc[mt][nt][0] + bb0;
            float v10 = acc[mt][nt][2] + bb0;
            stcs(out + o0, v00); stcs(out + o1, v10);
            zp[mt * 2 + 0] += fexp(v00); zp[mt * 2 + 1] += fexp(v10);
            if (n + 1 < VOC) {
                float bb1 = b2[n + 1];
                float v01 = acc[mt][nt][1] + bb1;
                float v11 = acc[mt][nt][3] + bb1;
                stcs(out + o0 + 1, v01); stcs(out + o1 + 1, v11);
                zp[mt * 2 + 0] += fexp(v01); zp[mt * 2 + 1] += fexp(v11);
            }
        }
    }
    #pragma unroll
    for (int mt = 0; mt < 2; mt++) {
        int m0 = bm + wm * 32 + mt * 16 + lq;
        atomicAdd(&g_z[m0],     zp[mt * 2 + 0]);
        atomicAdd(&g_z[m0 + 8], zp[mt * 2 + 1]);
    }
}

// ================= finalize: o_prob from logits + loss =================
__global__ void k_finalize(const int* __restrict__ targets, float* __restrict__ out) {
    int r = blockIdx.x;
    float rz = 1.0f / g_z[r];
    const float* lg = out + (size_t)r * VOC;
    float* op = out + PROB_OFF + (size_t)r * VOC;
    for (int c = threadIdx.x; c < VOC; c += 1024)
        stcs(op + c, fexp(ldcs(lg + c)) * rz);
    if (threadIdx.x == 0) {
        float logp = lg[targets[r]] - logf(g_z[r]);
        atomicAdd(out + LOSS_OFF, -logp * (1.0f / BT));
    }
}

// ================= host launch =================
extern "C" void kernel_launch(void* const* d_in, const int* in_sizes, int n_in,
                              void* d_out, int out_size) {
    const int*   idx     = (const int*)  d_in[0];
    const int*   targets = (const int*)  d_in[1];
    const float* tok_emb = (const float*)d_in[2];
    const float* pos_emb = (const float*)d_in[3];
    const float* Wq      = (const float*)d_in[4];
    const float* Wk      = (const float*)d_in[5];
    const float* Wv      = (const float*)d_in[6];
    const float* W1      = (const float*)d_in[7];
    const float* b1      = (const float*)d_in[8];
    const float* W2      = (const float*)d_in[9];
    const float* b2      = (const float*)d_in[10];
    float* out = (float*)d_out;

    cudaFuncSetAttribute(k_gemm_tc, cudaFuncAttributeMaxDynamicSharedMemorySize, GSMEM);
    cudaFuncSetAttribute(k_ff1d,    cudaFuncAttributeMaxDynamicSharedMemorySize, FF_SMEM);

    {   // launch 1: qkv + zeroing
        k_fused1<<<QKV_BLOCKS + ZERO_BLOCKS, 256>>>(idx, tok_emb, pos_emb,
                                                    Wq, Wk, Wv, out);
    }
    {   // launch 2: scores + W1T + first half of W2T (transpose hides under compute)
        k_score2x<<<NSCORE + W1T_TILES + W2T_HALF, 256>>>(W1, W2);
    }
    {   // launch 3: attention out + second half of W2T
        k_attnout3x<<<NATT + (W2T_TILES - W2T_HALF), 256>>>(W2);
    }
    {   // launch 4: FF1 via tensor cores (32-row tiles)
        dim3 g(BT / 32, HID / 64);
        k_ff1d<<<g, 256, FF_SMEM>>>(b1);
    }
    {   // launch 5: LM-head GEMM
        dim3 g(BT / MT, VOCP / NTL);
        k_gemm_tc<<<g, 256, GSMEM>>>(b2, out);
    }
    // launch 6: finalize
    k_finalize<<<BT, 1024>>>(targets, out);
}